// round 2
// baseline (speedup 1.0000x reference)
#include <cuda_runtime.h>
#include <cstdint>
#include <cstddef>

// Problem constants
#define NNODES 50000
#define NRELS  47
#define EMB    1600
#define WS     16
#define NCLS   50
#define NBASES 40
#define W1COLS (NRELS * WS)   // 752

// Scratch (device globals; no allocation allowed)
__device__ int   g_cnt[NRELS * NNODES];                 // 9.4 MB
__device__ float g_W1p[EMB * W1COLS];                   // 4.8 MB
__device__ float g_H[(size_t)NNODES * W1COLS];          // 150.4 MB
__device__ float g_h1[NNODES * WS];                     // 3.2 MB
__device__ float g_w2[NRELS * WS * NCLS];               // 150.4 KB

// ---------------------------------------------------------------------------
// helpers
// ---------------------------------------------------------------------------
__device__ __forceinline__ void red_add_v4(float* p, float a, float b, float c, float d) {
    asm volatile("red.global.add.v4.f32 [%0], {%1,%2,%3,%4};"
                 :: "l"(p), "f"(a), "f"(b), "f"(c), "f"(d) : "memory");
}
__device__ __forceinline__ void red_add_f32(float* p, float v) {
    asm volatile("red.global.add.f32 [%0], %1;" :: "l"(p), "f"(v) : "memory");
}

// ---------------------------------------------------------------------------
// zero / init
// ---------------------------------------------------------------------------
__global__ void zero_scratch_k() {
    int i = blockIdx.x * blockDim.x + threadIdx.x;
    if (i < NRELS * NNODES) g_cnt[i] = 0;
    if (i < NNODES * WS)    g_h1[i]  = 0.0f;
}

__global__ void init_out_k(float* __restrict__ out, const float* __restrict__ bias2) {
    int i = blockIdx.x * blockDim.x + threadIdx.x;
    if (i < NNODES * NCLS) out[i] = bias2[i % NCLS];
}

// ---------------------------------------------------------------------------
// per-column degree count
// ---------------------------------------------------------------------------
__global__ void count_k(const int* __restrict__ cols, int E) {
    int i = blockIdx.x * blockDim.x + threadIdx.x;
    if (i < E) atomicAdd(&g_cnt[cols[i]], 1);
}

// ---------------------------------------------------------------------------
// weight packing: fold comps into bases
// ---------------------------------------------------------------------------
__global__ void pack_w1_k(const float* __restrict__ comps1, const float* __restrict__ bases1) {
    int idx = blockIdx.x * blockDim.x + threadIdx.x;
    if (idx >= EMB * W1COLS) return;
    int i = idx / W1COLS;
    int j = idx - i * W1COLS;
    int r = j / WS;
    int o = j - r * WS;
    float s = 0.0f;
    #pragma unroll 8
    for (int b = 0; b < NBASES; b++)
        s += comps1[r * NBASES + b] * bases1[((size_t)b * EMB + i) * WS + o];
    g_W1p[idx] = s;
}

__global__ void pack_w2_k(const float* __restrict__ comps2, const float* __restrict__ bases2) {
    int idx = blockIdx.x * blockDim.x + threadIdx.x;
    if (idx >= NRELS * WS * NCLS) return;
    int r   = idx / (WS * NCLS);
    int rem = idx - r * (WS * NCLS);
    int k   = rem / NCLS;
    int c   = rem - k * NCLS;
    float s = 0.0f;
    #pragma unroll 8
    for (int b = 0; b < NBASES; b++)
        s += comps2[r * NBASES + b] * bases2[(b * WS + k) * NCLS + c];
    g_w2[idx] = s;
}

// ---------------------------------------------------------------------------
// SGEMM: H(50000 x 752) = emb(50000 x 1600) @ W1p(1600 x 752)
// 128x128 block tile, BK=16, 256 threads, 8x8 per thread, double-buffered smem
// ---------------------------------------------------------------------------
#define BM 128
#define BN 128
#define BK 16

__global__ void __launch_bounds__(256)
sgemm_k(const float* __restrict__ A, int M, int Ncols, int K) {
    __shared__ float As[2][BK][BM];
    __shared__ float Bs[2][BK][BN];

    const float* B = g_W1p;
    float*       C = g_H;

    int tid = threadIdx.x;
    int m0 = blockIdx.y * BM;
    int n0 = blockIdx.x * BN;
    int tx = tid & 15;          // 0..15 -> col groups
    int ty = tid >> 4;          // 0..15 -> row groups

    // A loader: thread loads 2 float4 (rows a_row, a_row+64; cols a_k4..a_k4+3)
    int a_row = tid >> 2;       // 0..63
    int a_k4  = (tid & 3) * 4;  // 0,4,8,12
    // B loader: thread loads 2 float4 (k rows b_k, b_k+8; cols b_n4..b_n4+3)
    int b_k   = tid >> 5;       // 0..7
    int b_n4  = (tid & 31) * 4; // 0..124

    float acc[8][8];
    #pragma unroll
    for (int i = 0; i < 8; i++)
        #pragma unroll
        for (int j = 0; j < 8; j++) acc[i][j] = 0.0f;

    float4 pa0, pa1, pb0, pb1;

    auto loadG = [&](int kt) {
        int k = kt * BK + a_k4;
        int m1 = m0 + a_row, m2 = m1 + 64;
        pa0 = (m1 < M) ? *(const float4*)(A + (size_t)m1 * K + k) : make_float4(0, 0, 0, 0);
        pa1 = (m2 < M) ? *(const float4*)(A + (size_t)m2 * K + k) : make_float4(0, 0, 0, 0);
        int n = n0 + b_n4;
        int k1 = kt * BK + b_k, k2 = k1 + 8;
        if (n + 3 < Ncols) {
            pb0 = *(const float4*)(B + (size_t)k1 * Ncols + n);
            pb1 = *(const float4*)(B + (size_t)k2 * Ncols + n);
        } else {
            float t0[4], t1[4];
            #pragma unroll
            for (int j = 0; j < 4; j++) {
                t0[j] = (n + j < Ncols) ? B[(size_t)k1 * Ncols + n + j] : 0.0f;
                t1[j] = (n + j < Ncols) ? B[(size_t)k2 * Ncols + n + j] : 0.0f;
            }
            pb0 = make_float4(t0[0], t0[1], t0[2], t0[3]);
            pb1 = make_float4(t1[0], t1[1], t1[2], t1[3]);
        }
    };
    auto storeS = [&](int buf) {
        float* a0 = (float*)&pa0;
        float* a1 = (float*)&pa1;
        #pragma unroll
        for (int j = 0; j < 4; j++) {
            As[buf][a_k4 + j][a_row]      = a0[j];
            As[buf][a_k4 + j][a_row + 64] = a1[j];
        }
        *(float4*)&Bs[buf][b_k][b_n4]     = pb0;
        *(float4*)&Bs[buf][b_k + 8][b_n4] = pb1;
    };

    int nkt = K / BK;   // 100
    loadG(0);
    storeS(0);
    __syncthreads();

    for (int kt = 0; kt < nkt; ++kt) {
        int cur = kt & 1;
        if (kt + 1 < nkt) loadG(kt + 1);
        #pragma unroll
        for (int k = 0; k < BK; k++) {
            float ar[8], br[8];
            *(float4*)&ar[0] = *(const float4*)&As[cur][k][ty * 4];
            *(float4*)&ar[4] = *(const float4*)&As[cur][k][ty * 4 + 64];
            *(float4*)&br[0] = *(const float4*)&Bs[cur][k][tx * 4];
            *(float4*)&br[4] = *(const float4*)&Bs[cur][k][tx * 4 + 64];
            #pragma unroll
            for (int i = 0; i < 8; i++)
                #pragma unroll
                for (int j = 0; j < 8; j++)
                    acc[i][j] += ar[i] * br[j];
        }
        if (kt + 1 < nkt) {
            storeS((kt + 1) & 1);
            __syncthreads();
        }
    }

    // epilogue
    #pragma unroll
    for (int i = 0; i < 8; i++) {
        int m = m0 + ty * 4 + ((i < 4) ? i : (64 + i - 4));
        if (m >= M) continue;
        #pragma unroll
        for (int jh = 0; jh < 2; jh++) {
            int n = n0 + tx * 4 + jh * 64;
            if (n + 3 < Ncols) {
                float4 v = make_float4(acc[i][jh * 4 + 0], acc[i][jh * 4 + 1],
                                       acc[i][jh * 4 + 2], acc[i][jh * 4 + 3]);
                *(float4*)(C + (size_t)m * Ncols + n) = v;
            } else {
                #pragma unroll
                for (int j2 = 0; j2 < 4; j2++)
                    if (n + j2 < Ncols) C[(size_t)m * Ncols + n + j2] = acc[i][jh * 4 + j2];
            }
        }
    }
}

// ---------------------------------------------------------------------------
// SpMM layer 1: h1[row] += (1/cnt[col]) * H[col%N, (col/N)*16 .. +16]
// ---------------------------------------------------------------------------
__global__ void spmm1_k(const int* __restrict__ rows, const int* __restrict__ cols, int E) {
    int e = blockIdx.x * blockDim.x + threadIdx.x;
    if (e >= E) return;
    int col = cols[e];
    int row = rows[e];
    unsigned r = (unsigned)col / NNODES;
    int n = col - (int)r * NNODES;
    float v = 1.0f / (float)g_cnt[col];
    const float4* src = (const float4*)(g_H + (size_t)n * W1COLS + r * WS);
    float* dst = g_h1 + (size_t)row * WS;
    #pragma unroll
    for (int q = 0; q < 4; q++) {
        float4 x = src[q];
        red_add_v4(dst + q * 4, v * x.x, v * x.y, v * x.z, v * x.w);
    }
}

__global__ void biasrelu_k(const float* __restrict__ bias1) {
    int i = blockIdx.x * blockDim.x + threadIdx.x;
    if (i >= NNODES * WS) return;
    float x = g_h1[i] + bias1[i & (WS - 1)];
    g_h1[i] = (x > 0.0f) ? x : 0.0f;
}

// ---------------------------------------------------------------------------
// SpMM layer 2 (fused dense transform): warp per edge, lanes over classes.
// w2 (47x16x50) resident in shared memory; conflict-free LDS (lanes read
// consecutive c). Accumulate into out via red.global.add.
// ---------------------------------------------------------------------------
#define W2ELEMS (NRELS * WS * NCLS)     // 37600
#define W2SMEM  ((W2ELEMS + 64) * 4)    // pad so unguarded OOB smem reads stay in-bounds

__global__ void __launch_bounds__(1024)
spmm2_k(const int* __restrict__ rows, const int* __restrict__ cols, int E,
        float* __restrict__ out) {
    extern __shared__ float w2s[];
    for (int i = threadIdx.x; i < W2ELEMS + 64; i += blockDim.x)
        w2s[i] = (i < W2ELEMS) ? g_w2[i] : 0.0f;
    __syncthreads();

    int lane = threadIdx.x & 31;
    int gw = (blockIdx.x * blockDim.x + threadIdx.x) >> 5;
    int nw = (gridDim.x * blockDim.x) >> 5;

    for (int e = gw; e < E; e += nw) {
        int col = cols[e];
        int row = rows[e];
        unsigned r = (unsigned)col / NNODES;
        int n = col - (int)r * NNODES;
        float v = 1.0f / (float)g_cnt[col];
        const float4* hp = (const float4*)(g_h1 + (size_t)n * WS);
        float4 h0 = hp[0], h1v = hp[1], h2 = hp[2], h3 = hp[3];
        const float* wr = w2s + r * (WS * NCLS);
        #pragma unroll
        for (int pass = 0; pass < 2; ++pass) {
            int c = lane + pass * 32;
            const float* w = wr + c;
            float acc;
            acc  = h0.x  * w[0]   + h0.y  * w[50]  + h0.z  * w[100] + h0.w  * w[150];
            acc += h1v.x * w[200] + h1v.y * w[250] + h1v.z * w[300] + h1v.w * w[350];
            acc += h2.x  * w[400] + h2.y  * w[450] + h2.z  * w[500] + h2.w  * w[550];
            acc += h3.x  * w[600] + h3.y  * w[650] + h3.z  * w[700] + h3.w  * w[750];
            if (c < NCLS) red_add_f32(out + (size_t)row * NCLS + c, v * acc);
        }
    }
}

// ---------------------------------------------------------------------------
// launch
// ---------------------------------------------------------------------------
extern "C" void kernel_launch(void* const* d_in, const int* in_sizes, int n_in,
                              void* d_out, int out_size) {
    const float* emb    = (const float*)d_in[0];
    const float* comps1 = (const float*)d_in[1];
    const float* bases1 = (const float*)d_in[2];
    const float* comps2 = (const float*)d_in[3];
    const float* bases2 = (const float*)d_in[4];
    const float* bias1  = (const float*)d_in[5];
    const float* bias2  = (const float*)d_in[6];
    const int*   rows   = (const int*)d_in[7];
    const int*   cols   = (const int*)d_in[8];
    float*       out    = (float*)d_out;
    int E = in_sizes[7];

    // init scratch + output
    zero_scratch_k<<<(NRELS * NNODES + 255) / 256, 256>>>();
    init_out_k<<<(NNODES * NCLS + 255) / 256, 256>>>(out, bias2);

    // degree counts
    count_k<<<(E + 255) / 256, 256>>>(cols, E);

    // fold comps into weights
    pack_w1_k<<<(EMB * W1COLS + 255) / 256, 256>>>(comps1, bases1);
    pack_w2_k<<<(W2ELEMS + 255) / 256, 256>>>(comps2, bases2);

    // layer-1 dense transform: H = emb @ W1p
    {
        dim3 grid((W1COLS + BN - 1) / BN, (NNODES + BM - 1) / BM);  // (6, 391)
        sgemm_k<<<grid, 256>>>(emb, NNODES, W1COLS, EMB);
    }

    // layer-1 sparse aggregation + activation
    spmm1_k<<<(E + 255) / 256, 256>>>(rows, cols, E);
    biasrelu_k<<<(NNODES * WS + 255) / 256, 256>>>(bias1);

    // layer-2 fused transform + aggregation
    cudaFuncSetAttribute(spmm2_k, cudaFuncAttributeMaxDynamicSharedMemorySize, W2SMEM);
    spmm2_k<<<148, 1024, W2SMEM>>>(rows, cols, E, out);
}

// round 3
// speedup vs baseline: 2.0727x; 2.0727x over previous
#include <cuda_runtime.h>
#include <cstdint>
#include <cstddef>

// Problem constants
#define NNODES 50000
#define NRELS  47
#define EMB    1600
#define WS     16
#define NCLS   50
#define NBASES 40
#define W1COLS (NRELS * WS)   // 752
#define NPAD   768            // padded N for the GEMM (752 -> 768, zero pad)

// Scratch (device globals; no allocation allowed)
__device__ int   g_cnt[NRELS * NNODES];                 // 9.4 MB
__device__ float g_W1p[EMB * NPAD];                     // 4.9 MB   [K][NPAD]
__device__ float g_H[(size_t)NNODES * NPAD];            // 153.6 MB [M][NPAD]
__device__ float g_h1[NNODES * WS];                     // 3.2 MB
__device__ float g_w2[NRELS * WS * NCLS];               // 150.4 KB

// ---------------------------------------------------------------------------
// helpers
// ---------------------------------------------------------------------------
__device__ __forceinline__ void red_add_v4(float* p, float a, float b, float c, float d) {
    asm volatile("red.global.add.v4.f32 [%0], {%1,%2,%3,%4};"
                 :: "l"(p), "f"(a), "f"(b), "f"(c), "f"(d) : "memory");
}
__device__ __forceinline__ void red_add_f32(float* p, float v) {
    asm volatile("red.global.add.f32 [%0], %1;" :: "l"(p), "f"(v) : "memory");
}
__device__ __forceinline__ unsigned f2tf(float f) {
    unsigned r;
    asm("cvt.rna.tf32.f32 %0, %1;" : "=r"(r) : "f"(f));
    return r;
}
__device__ __forceinline__ void mma_tf32(float* c, const unsigned* a, unsigned b0, unsigned b1) {
    asm volatile(
        "mma.sync.aligned.m16n8k8.row.col.f32.tf32.tf32.f32 "
        "{%0,%1,%2,%3}, {%4,%5,%6,%7}, {%8,%9}, {%0,%1,%2,%3};"
        : "+f"(c[0]), "+f"(c[1]), "+f"(c[2]), "+f"(c[3])
        : "r"(a[0]), "r"(a[1]), "r"(a[2]), "r"(a[3]), "r"(b0), "r"(b1));
}

// ---------------------------------------------------------------------------
// zero / init
// ---------------------------------------------------------------------------
__global__ void zero_scratch_k() {
    int i = blockIdx.x * blockDim.x + threadIdx.x;
    if (i < NRELS * NNODES) g_cnt[i] = 0;
    if (i < NNODES * WS)    g_h1[i]  = 0.0f;
}

__global__ void init_out_k(float* __restrict__ out, const float* __restrict__ bias2) {
    int i = blockIdx.x * blockDim.x + threadIdx.x;
    if (i < NNODES * NCLS) out[i] = bias2[i % NCLS];
}

// ---------------------------------------------------------------------------
// per-column degree count
// ---------------------------------------------------------------------------
__global__ void count_k(const int* __restrict__ cols, int E) {
    int i = blockIdx.x * blockDim.x + threadIdx.x;
    if (i < E) atomicAdd(&g_cnt[cols[i]], 1);
}

// ---------------------------------------------------------------------------
// weight packing: fold comps into bases.  W1p laid out [K=1600][NPAD=768].
// ---------------------------------------------------------------------------
__global__ void pack_w1_k(const float* __restrict__ comps1, const float* __restrict__ bases1) {
    int idx = blockIdx.x * blockDim.x + threadIdx.x;
    if (idx >= EMB * NPAD) return;
    int i = idx / NPAD;          // k index (emb dim)
    int j = idx - i * NPAD;      // output col
    if (j >= W1COLS) { g_W1p[idx] = 0.0f; return; }
    int r = j / WS;
    int o = j - r * WS;
    float s = 0.0f;
    #pragma unroll 8
    for (int b = 0; b < NBASES; b++)
        s += comps1[r * NBASES + b] * bases1[((size_t)b * EMB + i) * WS + o];
    g_W1p[idx] = s;
}

__global__ void pack_w2_k(const float* __restrict__ comps2, const float* __restrict__ bases2) {
    int idx = blockIdx.x * blockDim.x + threadIdx.x;
    if (idx >= NRELS * WS * NCLS) return;
    int r   = idx / (WS * NCLS);
    int rem = idx - r * (WS * NCLS);
    int k   = rem / NCLS;
    int c   = rem - k * NCLS;
    float s = 0.0f;
    #pragma unroll 8
    for (int b = 0; b < NBASES; b++)
        s += comps2[r * NBASES + b] * bases2[(b * WS + k) * NCLS + c];
    g_w2[idx] = s;
}

// ---------------------------------------------------------------------------
// TF32 tensor-core GEMM: g_H(50000 x 768) = emb(50000 x 1600) @ g_W1p(1600 x 768)
// BM=128 BN=256 BK=32, 256 threads, warp tile 64x64 (2x4 warps),
// fragment-order smem (conflict-free LDS.128), double buffered.
// ---------------------------------------------------------------------------
#define GBM 128
#define GBN 256
#define GBK 32
#define SA_ELEMS 4096   // 128*32
#define SB_ELEMS 8192   // 32*256

__global__ void __launch_bounds__(256, 1)
gemm_tf32_k(const float* __restrict__ A, int M) {
    extern __shared__ unsigned sm[];
    unsigned* sA = sm;                 // [2][SA_ELEMS]
    unsigned* sB = sm + 2 * SA_ELEMS;  // [2][SB_ELEMS]

    const int tid  = threadIdx.x;
    const int lane = tid & 31;
    const int warp = tid >> 5;
    const int wm = warp >> 2;   // 0..1
    const int wn = warp & 3;    // 0..3
    const int m0 = blockIdx.y * GBM;
    const int n0 = blockIdx.x * GBN;

    // producer assignments
    const int arow = tid >> 1;          // 0..127 (row in A tile)
    const int af4  = tid & 1;           // f4 idx = af4 + u*2, u=0..3
    const int brow = tid >> 3;          // 0..31  (k row in B tile)
    const int bf4  = tid & 7;           // f4 idx = bf4 + u*8, u=0..7

    float4 ra[4], rb[8];
    const bool aok = (m0 + arow) < M;

    float acc[4][8][4];
    #pragma unroll
    for (int i = 0; i < 4; i++)
        #pragma unroll
        for (int j = 0; j < 8; j++)
            #pragma unroll
            for (int q = 0; q < 4; q++) acc[i][j][q] = 0.0f;

    auto loadG = [&](int kt) {
        const int kb = kt * GBK;
        const float* Ap = A + (size_t)(m0 + arow) * EMB + kb;
        #pragma unroll
        for (int u = 0; u < 4; u++) {
            int f4 = af4 + u * 2;
            ra[u] = aok ? *(const float4*)(Ap + f4 * 4) : make_float4(0, 0, 0, 0);
        }
        const float* Bp = g_W1p + (size_t)(kb + brow) * NPAD + n0;
        #pragma unroll
        for (int u = 0; u < 8; u++) {
            int f4 = bf4 + u * 8;
            rb[u] = *(const float4*)(Bp + f4 * 4);
        }
    };

    auto stsA1 = [&](unsigned* dst, int kk, int rr, float v) {
        int s = kk >> 3, kr = kk & 7;
        int i = rr >> 4, ri = rr & 15;
        int l = ((ri & 7) << 2) | (kr & 3);
        int slot = ((kr >> 2) << 1) | (ri >> 3);
        dst[(((s * 8 + i) * 32 + l) << 2) + slot] = f2tf(v);
    };
    auto stsB1 = [&](unsigned* dst, int kk, int c, float v) {
        int s = kk >> 3, kr = kk & 7;
        int j = c >> 3, cl = c & 7;
        int l = (cl << 2) | (kr & 3);
        int slot = ((j & 1) << 1) | (kr >> 2);
        dst[(((s * 16 + (j >> 1)) * 32 + l) << 2) + slot] = f2tf(v);
    };
    auto storeS = [&](int buf) {
        unsigned* da = sA + buf * SA_ELEMS;
        unsigned* db = sB + buf * SB_ELEMS;
        #pragma unroll
        for (int u = 0; u < 4; u++) {
            int k4 = (af4 + u * 2) * 4;
            stsA1(da, k4 + 0, arow, ra[u].x);
            stsA1(da, k4 + 1, arow, ra[u].y);
            stsA1(da, k4 + 2, arow, ra[u].z);
            stsA1(da, k4 + 3, arow, ra[u].w);
        }
        #pragma unroll
        for (int u = 0; u < 8; u++) {
            int c4 = (bf4 + u * 8) * 4;
            stsB1(db, brow, c4 + 0, rb[u].x);
            stsB1(db, brow, c4 + 1, rb[u].y);
            stsB1(db, brow, c4 + 2, rb[u].z);
            stsB1(db, brow, c4 + 3, rb[u].w);
        }
    };

    const int NKT = EMB / GBK;  // 50
    loadG(0);
    storeS(0);
    __syncthreads();

    for (int kt = 0; kt < NKT; ++kt) {
        const int cur = kt & 1;
        if (kt + 1 < NKT) loadG(kt + 1);
        const unsigned* pa = sA + cur * SA_ELEMS;
        const unsigned* pb = sB + cur * SB_ELEMS;
        #pragma unroll
        for (int s = 0; s < 4; s++) {
            unsigned afr[4][4], bfr[4][4];
            #pragma unroll
            for (int im = 0; im < 4; im++) {
                int i = wm * 4 + im;
                *(uint4*)afr[im] = *(const uint4*)(pa + ((s * 8 + i) * 32 + lane) * 4);
            }
            #pragma unroll
            for (int jj = 0; jj < 4; jj++) {
                int j2 = wn * 4 + jj;
                *(uint4*)bfr[jj] = *(const uint4*)(pb + ((s * 16 + j2) * 32 + lane) * 4);
            }
            #pragma unroll
            for (int im = 0; im < 4; im++)
                #pragma unroll
                for (int jj = 0; jj < 4; jj++) {
                    mma_tf32(acc[im][jj * 2 + 0], afr[im], bfr[jj][0], bfr[jj][1]);
                    mma_tf32(acc[im][jj * 2 + 1], afr[im], bfr[jj][2], bfr[jj][3]);
                }
        }
        if (kt + 1 < NKT) {
            storeS((kt + 1) & 1);
            __syncthreads();
        }
    }

    // epilogue: c0=C[r][c] c1=C[r][c+1] c2=C[r+8][c] c3=C[r+8][c+1]
    const int rl = lane >> 2;
    const int cl2 = (lane & 3) * 2;
    #pragma unroll
    for (int im = 0; im < 4; im++) {
        int row = m0 + (wm * 4 + im) * 16 + rl;
        #pragma unroll
        for (int jn = 0; jn < 8; jn++) {
            int col = n0 + (wn * 8 + jn) * 8 + cl2;
            float* p = g_H + (size_t)row * NPAD + col;
            if (row < M)     *(float2*)p              = make_float2(acc[im][jn][0], acc[im][jn][1]);
            if (row + 8 < M) *(float2*)(p + 8 * NPAD) = make_float2(acc[im][jn][2], acc[im][jn][3]);
        }
    }
}

// ---------------------------------------------------------------------------
// SpMM layer 1: h1[row] += (1/cnt[col]) * H[col%N, (col/N)*16 .. +16]
// ---------------------------------------------------------------------------
__global__ void spmm1_k(const int* __restrict__ rows, const int* __restrict__ cols, int E) {
    int e = blockIdx.x * blockDim.x + threadIdx.x;
    if (e >= E) return;
    int col = cols[e];
    int row = rows[e];
    unsigned r = (unsigned)col / NNODES;
    int n = col - (int)r * NNODES;
    float v = 1.0f / (float)g_cnt[col];
    const float4* src = (const float4*)(g_H + (size_t)n * NPAD + r * WS);
    float* dst = g_h1 + (size_t)row * WS;
    #pragma unroll
    for (int q = 0; q < 4; q++) {
        float4 x = src[q];
        red_add_v4(dst + q * 4, v * x.x, v * x.y, v * x.z, v * x.w);
    }
}

__global__ void biasrelu_k(const float* __restrict__ bias1) {
    int i = blockIdx.x * blockDim.x + threadIdx.x;
    if (i >= NNODES * WS) return;
    float x = g_h1[i] + bias1[i & (WS - 1)];
    g_h1[i] = (x > 0.0f) ? x : 0.0f;
}

// ---------------------------------------------------------------------------
// SpMM layer 2 (fused dense transform): warp per edge, lanes over classes.
// ---------------------------------------------------------------------------
#define W2ELEMS (NRELS * WS * NCLS)     // 37600
#define W2SMEM  ((W2ELEMS + 64) * 4)

__global__ void __launch_bounds__(1024)
spmm2_k(const int* __restrict__ rows, const int* __restrict__ cols, int E,
        float* __restrict__ out) {
    extern __shared__ float w2s[];
    for (int i = threadIdx.x; i < W2ELEMS + 64; i += blockDim.x)
        w2s[i] = (i < W2ELEMS) ? g_w2[i] : 0.0f;
    __syncthreads();

    int lane = threadIdx.x & 31;
    int gw = (blockIdx.x * blockDim.x + threadIdx.x) >> 5;
    int nw = (gridDim.x * blockDim.x) >> 5;

    for (int e = gw; e < E; e += nw) {
        int col = cols[e];
        int row = rows[e];
        unsigned r = (unsigned)col / NNODES;
        int n = col - (int)r * NNODES;
        float v = 1.0f / (float)g_cnt[col];
        const float4* hp = (const float4*)(g_h1 + (size_t)n * WS);
        float4 h0 = hp[0], h1v = hp[1], h2 = hp[2], h3 = hp[3];
        const float* wr = w2s + r * (WS * NCLS);
        #pragma unroll
        for (int pass = 0; pass < 2; ++pass) {
            int c = lane + pass * 32;
            const float* w = wr + c;
            float acc;
            acc  = h0.x  * w[0]   + h0.y  * w[50]  + h0.z  * w[100] + h0.w  * w[150];
            acc += h1v.x * w[200] + h1v.y * w[250] + h1v.z * w[300] + h1v.w * w[350];
            acc += h2.x  * w[400] + h2.y  * w[450] + h2.z  * w[500] + h2.w  * w[550];
            acc += h3.x  * w[600] + h3.y  * w[650] + h3.z  * w[700] + h3.w  * w[750];
            if (c < NCLS) red_add_f32(out + (size_t)row * NCLS + c, v * acc);
        }
    }
}

// ---------------------------------------------------------------------------
// launch
// ---------------------------------------------------------------------------
extern "C" void kernel_launch(void* const* d_in, const int* in_sizes, int n_in,
                              void* d_out, int out_size) {
    const float* emb    = (const float*)d_in[0];
    const float* comps1 = (const float*)d_in[1];
    const float* bases1 = (const float*)d_in[2];
    const float* comps2 = (const float*)d_in[3];
    const float* bases2 = (const float*)d_in[4];
    const float* bias1  = (const float*)d_in[5];
    const float* bias2  = (const float*)d_in[6];
    const int*   rows   = (const int*)d_in[7];
    const int*   cols   = (const int*)d_in[8];
    float*       out    = (float*)d_out;
    int E = in_sizes[7];

    // init scratch + output
    zero_scratch_k<<<(NRELS * NNODES + 255) / 256, 256>>>();
    init_out_k<<<(NNODES * NCLS + 255) / 256, 256>>>(out, bias2);

    // degree counts
    count_k<<<(E + 255) / 256, 256>>>(cols, E);

    // fold comps into weights
    pack_w1_k<<<(EMB * NPAD + 255) / 256, 256>>>(comps1, bases1);
    pack_w2_k<<<(W2ELEMS + 255) / 256, 256>>>(comps2, bases2);

    // layer-1 dense transform: H = emb @ W1p  (TF32 tensor cores)
    {
        static int smem_set = 0;
        if (!smem_set) {
            cudaFuncSetAttribute(gemm_tf32_k, cudaFuncAttributeMaxDynamicSharedMemorySize,
                                 (2 * SA_ELEMS + 2 * SB_ELEMS) * 4);
            cudaFuncSetAttribute(spmm2_k, cudaFuncAttributeMaxDynamicSharedMemorySize, W2SMEM);
            smem_set = 1;
        }
        dim3 grid(NPAD / GBN, (NNODES + GBM - 1) / GBM);  // (3, 391)
        gemm_tf32_k<<<grid, 256, (2 * SA_ELEMS + 2 * SB_ELEMS) * 4>>>(emb, NNODES);
    }

    // layer-1 sparse aggregation + activation
    spmm1_k<<<(E + 255) / 256, 256>>>(rows, cols, E);
    biasrelu_k<<<(NNODES * WS + 255) / 256, 256>>>(bias1);

    // layer-2 fused transform + aggregation
    spmm2_k<<<148, 1024, W2SMEM>>>(rows, cols, E, out);
}

// round 10
// speedup vs baseline: 2.3724x; 1.1446x over previous
#include <cuda_runtime.h>
#include <cstdint>
#include <cstddef>

// Problem constants
#define NNODES 50000
#define NRELS  47
#define EMB    1600
#define WS     16
#define NCLS   50
#define NBASES 40
#define W1COLS (NRELS * WS)   // 752
#define NPAD   768            // padded N (752 -> 768, zero pad)
#define MBLKS  391            // ceil(50000/128)

// Scratch (device globals; no allocation allowed)
__device__ int   g_cnt[NRELS * NNODES];                   // 9.4 MB
__device__ float g_W1p[(size_t)NPAD * EMB];               // 4.9 MB  fragment-order tf32
__device__ float g_Af[(size_t)MBLKS * 200 * 1024];        // 320 MB  fragment-order tf32 A
__device__ float g_H[(size_t)NNODES * NPAD];              // 153.6 MB [M][NPAD]
__device__ float g_h1[NNODES * WS];                       // 3.2 MB
__device__ float g_w2[NRELS * WS * NCLS];                 // 150.4 KB

// ---------------------------------------------------------------------------
// helpers
// ---------------------------------------------------------------------------
__device__ __forceinline__ void red_add_v4(float* p, float a, float b, float c, float d) {
    asm volatile("red.global.add.v4.f32 [%0], {%1,%2,%3,%4};"
                 :: "l"(p), "f"(a), "f"(b), "f"(c), "f"(d) : "memory");
}
__device__ __forceinline__ void red_add_f32(float* p, float v) {
    asm volatile("red.global.add.f32 [%0], %1;" :: "l"(p), "f"(v) : "memory");
}
__device__ __forceinline__ unsigned f2tf(float f) {
    unsigned r;
    asm("cvt.rna.tf32.f32 %0, %1;" : "=r"(r) : "f"(f));
    return r;
}
__device__ __forceinline__ uint32_t smem_u32(const void* p) {
    uint32_t a;
    asm("{ .reg .u64 t; cvta.to.shared.u64 t, %1; cvt.u32.u64 %0, t; }" : "=r"(a) : "l"(p));
    return a;
}
__device__ __forceinline__ void mma_tf32(float* c, const unsigned* a, unsigned b0, unsigned b1) {
    asm volatile(
        "mma.sync.aligned.m16n8k8.row.col.f32.tf32.tf32.f32 "
        "{%0,%1,%2,%3}, {%4,%5,%6,%7}, {%8,%9}, {%0,%1,%2,%3};"
        : "+f"(c[0]), "+f"(c[1]), "+f"(c[2]), "+f"(c[3])
        : "r"(a[0]), "r"(a[1]), "r"(a[2]), "r"(a[3]), "r"(b0), "r"(b1));
}
#define CP_ASYNC16(sm, gp) \
    asm volatile("cp.async.cg.shared.global [%0], [%1], 16;" :: "r"(sm), "l"(gp) : "memory")
#define CP_COMMIT() asm volatile("cp.async.commit_group;" ::: "memory")
#define CP_WAIT(n)  asm volatile("cp.async.wait_group %0;" :: "n"(n) : "memory")

// ---------------------------------------------------------------------------
// zero / init
// ---------------------------------------------------------------------------
__global__ void zero_scratch_k() {
    int i = blockIdx.x * blockDim.x + threadIdx.x;
    if (i < NRELS * NNODES) g_cnt[i] = 0;
    if (i < NNODES * WS)    g_h1[i]  = 0.0f;
}

__global__ void init_out_k(float* __restrict__ out, const float* __restrict__ bias2) {
    int i = blockIdx.x * blockDim.x + threadIdx.x;
    if (i < NNODES * NCLS) out[i] = bias2[i % NCLS];
}

// ---------------------------------------------------------------------------
// per-column degree count
// ---------------------------------------------------------------------------
__global__ void count_k(const int* __restrict__ cols, int E) {
    int i = blockIdx.x * blockDim.x + threadIdx.x;
    if (i < E) atomicAdd(&g_cnt[cols[i]], 1);
}

// ---------------------------------------------------------------------------
// A conversion: emb (row-major fp32) -> g_Af (fragment-order tf32).
// Layout (uint4 units): [mb][sg(0..199)][i(0..7)][lane(0..31)], each uint4 =
//   slots {(r,k),(r+8,k),(r,k+4),(r+8,k+4)} with r = mb*128+i*16+(lane>>2),
//   k = sg*8 + (lane&3).
// ---------------------------------------------------------------------------
#define AF_U4 (MBLKS * 200 * 8 * 32)    // 20,019,200 uint4

__global__ void cvtA_k(const float* __restrict__ A) {
    unsigned idx = blockIdx.x * blockDim.x + threadIdx.x;
    if (idx >= AF_U4) return;
    int l  = idx & 31;
    int i  = (idx >> 5) & 7;
    int sg = (idx >> 8) % 200;
    int mb = idx / (200 * 256);
    int row = mb * 128 + i * 16 + (l >> 2);
    int k   = sg * 8 + (l & 3);
    bool ok0 = row < NNODES;
    bool ok1 = (row + 8) < NNODES;
    const float* p0 = A + (size_t)row * EMB + k;
    const float* p1 = A + (size_t)(row + 8) * EMB + k;
    uint4 v;
    v.x = ok0 ? f2tf(p0[0]) : 0u;
    v.y = ok1 ? f2tf(p1[0]) : 0u;
    v.z = ok0 ? f2tf(p0[4]) : 0u;
    v.w = ok1 ? f2tf(p1[4]) : 0u;
    ((uint4*)g_Af)[idx] = v;
}

// ---------------------------------------------------------------------------
// weight packing: fold comps into bases, emit fragment-order tf32.
// g_W1p float linear = [nb(0..2)][sg(0..199)][jp(0..15)][lane][slot]:
//   j = jp*2 + (slot>>1); n = nb*256 + j*8 + (lane>>2);
//   k = sg*8 + ((slot&1)<<2) + (lane&3).
// ---------------------------------------------------------------------------
__global__ void pack_w1_k(const float* __restrict__ comps1, const float* __restrict__ bases1) {
    int idx = blockIdx.x * blockDim.x + threadIdx.x;
    if (idx >= NPAD * EMB) return;
    int slot = idx & 3;
    int lane = (idx >> 2) & 31;
    int jp   = (idx >> 7) & 15;
    int sg   = (idx >> 11) % 200;
    int nb   = idx / 409600;
    int j = jp * 2 + (slot >> 1);
    int n = nb * 256 + j * 8 + (lane >> 2);
    int k = sg * 8 + ((slot & 1) << 2) + (lane & 3);
    if (n >= W1COLS) { g_W1p[idx] = 0.0f; return; }
    int r = n / WS;
    int o = n - r * WS;
    float s = 0.0f;
    #pragma unroll 8
    for (int b = 0; b < NBASES; b++)
        s += comps1[r * NBASES + b] * bases1[((size_t)b * EMB + k) * WS + o];
    g_W1p[idx] = __uint_as_float(f2tf(s));
}

__global__ void pack_w2_k(const float* __restrict__ comps2, const float* __restrict__ bases2) {
    int idx = blockIdx.x * blockDim.x + threadIdx.x;
    if (idx >= NRELS * WS * NCLS) return;
    int r   = idx / (WS * NCLS);
    int rem = idx - r * (WS * NCLS);
    int k   = rem / NCLS;
    int c   = rem - k * NCLS;
    float s = 0.0f;
    #pragma unroll 8
    for (int b = 0; b < NBASES; b++)
        s += comps2[r * NBASES + b] * bases2[(b * WS + k) * NCLS + c];
    g_w2[idx] = s;
}

// ---------------------------------------------------------------------------
// TF32 tensor-core GEMM (mma.sync), fragment-order operands via cp.async.
// g_H(50000 x 768) = emb @ W1.  BM=128 BN=256 BK=32, 256 thr, warp tile 64x64,
// 4-stage cp.async pipeline.
// ---------------------------------------------------------------------------
#define STG_A_BYTES 16384                   // 128x32 tf32
#define STG_B_BYTES 32768                   // 32x256 tf32
#define STG_BYTES   (STG_A_BYTES + STG_B_BYTES)
#define STG_FLOATS  (STG_BYTES / 4)         // 12288
#define GEMM_SMEM   (4 * STG_BYTES)         // 196608
#define NKT 50

__global__ void __launch_bounds__(256, 1)
gemm_tc_k(int M) {
    extern __shared__ float smemf[];
    const uint32_t sbase = smem_u32(smemf);
    const int tid  = threadIdx.x;
    const int lane = tid & 31;
    const int warp = tid >> 5;
    const int wm = warp >> 2;   // 0..1
    const int wn = warp & 3;    // 0..3
    const int nb = blockIdx.x;  // 0..2
    const int mb = blockIdx.y;  // 0..390
    const int m0 = mb * 128;
    const int n0 = nb * 256;

    const float* Abase = g_Af  + (size_t)mb * 204800;
    const float* Bbase = g_W1p + (size_t)nb * 409600;

    float acc[4][8][4];
    #pragma unroll
    for (int i = 0; i < 4; i++)
        #pragma unroll
        for (int j = 0; j < 8; j++)
            #pragma unroll
            for (int q = 0; q < 4; q++) acc[i][j][q] = 0.0f;

    auto issue = [&](int kt, int slot) {
        const uint32_t sa = sbase + slot * STG_BYTES;
        const float* ga = Abase + (size_t)kt * 4096;
        #pragma unroll
        for (int q = 0; q < 4; q++)
            CP_ASYNC16(sa + tid * 16 + q * 4096, ga + tid * 4 + q * 1024);
        const uint32_t sb = sa + STG_A_BYTES;
        const float* gb = Bbase + (size_t)kt * 8192;
        #pragma unroll
        for (int q = 0; q < 8; q++)
            CP_ASYNC16(sb + tid * 16 + q * 4096, gb + tid * 4 + q * 1024);
    };

    #pragma unroll
    for (int p = 0; p < 4; p++) { issue(p, p); CP_COMMIT(); }

    for (int kt = 0; kt < NKT; ++kt) {
        CP_WAIT(2);
        __syncthreads();
        const float* ps = smemf + (kt & 3) * STG_FLOATS;
        const float* pa = ps;
        const float* pb = ps + 4096;
        #pragma unroll
        for (int s = 0; s < 4; s++) {
            uint4 afr[4], bfr[4];
            #pragma unroll
            for (int im = 0; im < 4; im++) {
                int i = wm * 4 + im;
                afr[im] = *(const uint4*)(pa + ((s * 8 + i) * 32 + lane) * 4);
            }
            #pragma unroll
            for (int jj = 0; jj < 4; jj++) {
                int j2 = wn * 4 + jj;
                bfr[jj] = *(const uint4*)(pb + ((s * 16 + j2) * 32 + lane) * 4);
            }
            #pragma unroll
            for (int im = 0; im < 4; im++)
                #pragma unroll
                for (int jj = 0; jj < 4; jj++) {
                    mma_tf32(acc[im][jj * 2 + 0], (const unsigned*)&afr[im], bfr[jj].x, bfr[jj].y);
                    mma_tf32(acc[im][jj * 2 + 1], (const unsigned*)&afr[im], bfr[jj].z, bfr[jj].w);
                }
        }
        __syncthreads();
        if (kt + 4 < NKT) issue(kt + 4, kt & 3);
        CP_COMMIT();
    }

    // epilogue: c0=C[r][c] c1=C[r][c+1] c2=C[r+8][c] c3=C[r+8][c+1]
    const int rl = lane >> 2;
    const int cl2 = (lane & 3) * 2;
    #pragma unroll
    for (int im = 0; im < 4; im++) {
        int row = m0 + (wm * 4 + im) * 16 + rl;
        #pragma unroll
        for (int jn = 0; jn < 8; jn++) {
            int col = n0 + (wn * 8 + jn) * 8 + cl2;
            float* p = g_H + (size_t)row * NPAD + col;
            if (row < M)     *(float2*)p              = make_float2(acc[im][jn][0], acc[im][jn][1]);
            if (row + 8 < M) *(float2*)(p + 8 * NPAD) = make_float2(acc[im][jn][2], acc[im][jn][3]);
        }
    }
}

// ---------------------------------------------------------------------------
// SpMM layer 1: h1[row] += (1/cnt[col]) * H[col%N, (col/N)*16 .. +16]
// ---------------------------------------------------------------------------
__global__ void spmm1_k(const int* __restrict__ rows, const int* __restrict__ cols, int E) {
    int e = blockIdx.x * blockDim.x + threadIdx.x;
    if (e >= E) return;
    int col = cols[e];
    int row = rows[e];
    unsigned r = (unsigned)col / NNODES;
    int n = col - (int)r * NNODES;
    float v = 1.0f / (float)g_cnt[col];
    const float4* src = (const float4*)(g_H + (size_t)n * NPAD + r * WS);
    float* dst = g_h1 + (size_t)row * WS;
    #pragma unroll
    for (int q = 0; q < 4; q++) {
        float4 x = src[q];
        red_add_v4(dst + q * 4, v * x.x, v * x.y, v * x.z, v * x.w);
    }
}

__global__ void biasrelu_k(const float* __restrict__ bias1) {
    int i = blockIdx.x * blockDim.x + threadIdx.x;
    if (i >= NNODES * WS) return;
    float x = g_h1[i] + bias1[i & (WS - 1)];
    g_h1[i] = (x > 0.0f) ? x : 0.0f;
}

// ---------------------------------------------------------------------------
// SpMM layer 2 (fused dense transform): warp per edge, lanes over classes.
// ---------------------------------------------------------------------------
#define W2ELEMS (NRELS * WS * NCLS)     // 37600
#define W2SMEM  ((W2ELEMS + 64) * 4)

__global__ void __launch_bounds__(1024)
spmm2_k(const int* __restrict__ rows, const int* __restrict__ cols, int E,
        float* __restrict__ out) {
    extern __shared__ float w2s[];
    for (int i = threadIdx.x; i < W2ELEMS + 64; i += blockDim.x)
        w2s[i] = (i < W2ELEMS) ? g_w2[i] : 0.0f;
    __syncthreads();

    int lane = threadIdx.x & 31;
    int gw = (blockIdx.x * blockDim.x + threadIdx.x) >> 5;
    int nw = (gridDim.x * blockDim.x) >> 5;

    for (int e = gw; e < E; e += nw) {
        int col = cols[e];
        int row = rows[e];
        unsigned r = (unsigned)col / NNODES;
        int n = col - (int)r * NNODES;
        float v = 1.0f / (float)g_cnt[col];
        const float4* hp = (const float4*)(g_h1 + (size_t)n * WS);
        float4 h0 = hp[0], h1v = hp[1], h2 = hp[2], h3 = hp[3];
        const float* wr = w2s + r * (WS * NCLS);
        #pragma unroll
        for (int pass = 0; pass < 2; ++pass) {
            int c = lane + pass * 32;
            const float* w = wr + c;
            float acc;
            acc  = h0.x  * w[0]   + h0.y  * w[50]  + h0.z  * w[100] + h0.w  * w[150];
            acc += h1v.x * w[200] + h1v.y * w[250] + h1v.z * w[300] + h1v.w * w[350];
            acc += h2.x  * w[400] + h2.y  * w[450] + h2.z  * w[500] + h2.w  * w[550];
            acc += h3.x  * w[600] + h3.y  * w[650] + h3.z  * w[700] + h3.w  * w[750];
            if (c < NCLS) red_add_f32(out + (size_t)row * NCLS + c, v * acc);
        }
    }
}

// ---------------------------------------------------------------------------
// launch
// ---------------------------------------------------------------------------
extern "C" void kernel_launch(void* const* d_in, const int* in_sizes, int n_in,
                              void* d_out, int out_size) {
    const float* emb    = (const float*)d_in[0];
    const float* comps1 = (const float*)d_in[1];
    const float* bases1 = (const float*)d_in[2];
    const float* comps2 = (const float*)d_in[3];
    const float* bases2 = (const float*)d_in[4];
    const float* bias1  = (const float*)d_in[5];
    const float* bias2  = (const float*)d_in[6];
    const int*   rows   = (const int*)d_in[7];
    const int*   cols   = (const int*)d_in[8];
    float*       out    = (float*)d_out;
    int E = in_sizes[7];

    static int attr_set = 0;
    if (!attr_set) {
        cudaFuncSetAttribute(gemm_tc_k, cudaFuncAttributeMaxDynamicSharedMemorySize, GEMM_SMEM);
        cudaFuncSetAttribute(spmm2_k, cudaFuncAttributeMaxDynamicSharedMemorySize, W2SMEM);
        attr_set = 1;
    }

    // init scratch + output
    zero_scratch_k<<<(NRELS * NNODES + 255) / 256, 256>>>();
    init_out_k<<<(NNODES * NCLS + 255) / 256, 256>>>(out, bias2);

    // degree counts
    count_k<<<(E + 255) / 256, 256>>>(cols, E);

    // operand preparation (fragment-order tf32)
    cvtA_k<<<(AF_U4 + 255) / 256, 256>>>(emb);
    pack_w1_k<<<(NPAD * EMB + 255) / 256, 256>>>(comps1, bases1);
    pack_w2_k<<<(W2ELEMS + 255) / 256, 256>>>(comps2, bases2);

    // layer-1 dense transform: H = emb @ W1  (tf32 mma.sync, cp.async pipeline)
    {
        dim3 grid(NPAD / 256, MBLKS);  // (3, 391)
        gemm_tc_k<<<grid, 256, GEMM_SMEM>>>(NNODES);
    }

    // layer-1 sparse aggregation + activation
    spmm1_k<<<(E + 255) / 256, 256>>>(rows, cols, E);
    biasrelu_k<<<(NNODES * WS + 255) / 256, 256>>>(bias1);

    // layer-2 fused transform + aggregation
    spmm2_k<<<148, 1024, W2SMEM>>>(rows, cols, E, out);
}

// round 11
// speedup vs baseline: 2.8506x; 1.2016x over previous
#include <cuda_runtime.h>
#include <cstdint>
#include <cstddef>

// Problem constants
#define NNODES 50000
#define NRELS  47
#define EMB    1600
#define WS     16
#define NCLS   50
#define NCPAD  52             // padded classes so 4-col groups are 16B aligned
#define NBASES 40
#define W1COLS (NRELS * WS)   // 752
#define NPAD   768            // padded N (752 -> 768, zero pad)
#define MBLKS  391            // ceil(50000/128)

// Scratch (device globals; no allocation allowed)
__device__ int   g_cnt[NRELS * NNODES];                   // 9.4 MB
__device__ float g_W1p[(size_t)NPAD * EMB];               // 4.9 MB  fragment-order tf32
__device__ float g_Af[(size_t)MBLKS * 200 * 1024];        // 320 MB  fragment-order tf32 A
__device__ float g_H[(size_t)NNODES * NPAD];              // 153.6 MB [M][NPAD]
__device__ float g_h1[NNODES * WS];                       // 3.2 MB
__device__ float g_w2[NRELS * WS * NCLS];                 // 150.4 KB
__device__ float g_out2[(size_t)NNODES * NCPAD];          // 10.4 MB padded output accum

// ---------------------------------------------------------------------------
// helpers
// ---------------------------------------------------------------------------
__device__ __forceinline__ void red_add_v4(float* p, float a, float b, float c, float d) {
    asm volatile("red.global.add.v4.f32 [%0], {%1,%2,%3,%4};"
                 :: "l"(p), "f"(a), "f"(b), "f"(c), "f"(d) : "memory");
}
__device__ __forceinline__ unsigned f2tf(float f) {
    unsigned r;
    asm("cvt.rna.tf32.f32 %0, %1;" : "=r"(r) : "f"(f));
    return r;
}
__device__ __forceinline__ uint32_t smem_u32(const void* p) {
    uint32_t a;
    asm("{ .reg .u64 t; cvta.to.shared.u64 t, %1; cvt.u32.u64 %0, t; }" : "=r"(a) : "l"(p));
    return a;
}
__device__ __forceinline__ void mma_tf32(float* c, const unsigned* a, unsigned b0, unsigned b1) {
    asm volatile(
        "mma.sync.aligned.m16n8k8.row.col.f32.tf32.tf32.f32 "
        "{%0,%1,%2,%3}, {%4,%5,%6,%7}, {%8,%9}, {%0,%1,%2,%3};"
        : "+f"(c[0]), "+f"(c[1]), "+f"(c[2]), "+f"(c[3])
        : "r"(a[0]), "r"(a[1]), "r"(a[2]), "r"(a[3]), "r"(b0), "r"(b1));
}
#define CP_ASYNC16(sm, gp) \
    asm volatile("cp.async.cg.shared.global [%0], [%1], 16;" :: "r"(sm), "l"(gp) : "memory")
#define CP_COMMIT() asm volatile("cp.async.commit_group;" ::: "memory")
#define CP_WAIT(n)  asm volatile("cp.async.wait_group %0;" :: "n"(n) : "memory")

// ---------------------------------------------------------------------------
// zero / init
// ---------------------------------------------------------------------------
#define ZTOT (NNODES * NCPAD)   // 2.6M, largest of the three
__global__ void zero_scratch_k() {
    int i = blockIdx.x * blockDim.x + threadIdx.x;
    if (i < NRELS * NNODES) g_cnt[i] = 0;
    if (i < NNODES * WS)    g_h1[i]  = 0.0f;
    if (i < ZTOT)           g_out2[i] = 0.0f;
}

// ---------------------------------------------------------------------------
// per-column degree count
// ---------------------------------------------------------------------------
__global__ void count_k(const int* __restrict__ cols, int E) {
    int i = blockIdx.x * blockDim.x + threadIdx.x;
    if (i < E) atomicAdd(&g_cnt[cols[i]], 1);
}

// ---------------------------------------------------------------------------
// A conversion: emb (row-major fp32) -> g_Af (fragment-order tf32).
// ---------------------------------------------------------------------------
#define AF_U4 (MBLKS * 200 * 8 * 32)    // 20,019,200 uint4

__global__ void cvtA_k(const float* __restrict__ A) {
    unsigned idx = blockIdx.x * blockDim.x + threadIdx.x;
    if (idx >= AF_U4) return;
    int l  = idx & 31;
    int i  = (idx >> 5) & 7;
    int sg = (idx >> 8) % 200;
    int mb = idx / (200 * 256);
    int row = mb * 128 + i * 16 + (l >> 2);
    int k   = sg * 8 + (l & 3);
    bool ok0 = row < NNODES;
    bool ok1 = (row + 8) < NNODES;
    const float* p0 = A + (size_t)row * EMB + k;
    const float* p1 = A + (size_t)(row + 8) * EMB + k;
    uint4 v;
    v.x = ok0 ? f2tf(p0[0]) : 0u;
    v.y = ok1 ? f2tf(p1[0]) : 0u;
    v.z = ok0 ? f2tf(p0[4]) : 0u;
    v.w = ok1 ? f2tf(p1[4]) : 0u;
    ((uint4*)g_Af)[idx] = v;
}

// ---------------------------------------------------------------------------
// weight packing (fragment-order tf32 for W1)
// ---------------------------------------------------------------------------
__global__ void pack_w1_k(const float* __restrict__ comps1, const float* __restrict__ bases1) {
    int idx = blockIdx.x * blockDim.x + threadIdx.x;
    if (idx >= NPAD * EMB) return;
    int slot = idx & 3;
    int lane = (idx >> 2) & 31;
    int jp   = (idx >> 7) & 15;
    int sg   = (idx >> 11) % 200;
    int nb   = idx / 409600;
    int j = jp * 2 + (slot >> 1);
    int n = nb * 256 + j * 8 + (lane >> 2);
    int k = sg * 8 + ((slot & 1) << 2) + (lane & 3);
    if (n >= W1COLS) { g_W1p[idx] = 0.0f; return; }
    int r = n / WS;
    int o = n - r * WS;
    float s = 0.0f;
    #pragma unroll 8
    for (int b = 0; b < NBASES; b++)
        s += comps1[r * NBASES + b] * bases1[((size_t)b * EMB + k) * WS + o];
    g_W1p[idx] = __uint_as_float(f2tf(s));
}

__global__ void pack_w2_k(const float* __restrict__ comps2, const float* __restrict__ bases2) {
    int idx = blockIdx.x * blockDim.x + threadIdx.x;
    if (idx >= NRELS * WS * NCLS) return;
    int r   = idx / (WS * NCLS);
    int rem = idx - r * (WS * NCLS);
    int k   = rem / NCLS;
    int c   = rem - k * NCLS;
    float s = 0.0f;
    #pragma unroll 8
    for (int b = 0; b < NBASES; b++)
        s += comps2[r * NBASES + b] * bases2[(b * WS + k) * NCLS + c];
    g_w2[idx] = s;
}

// ---------------------------------------------------------------------------
// TF32 tensor-core GEMM (mma.sync), fragment-order operands via cp.async.
// ---------------------------------------------------------------------------
#define STG_A_BYTES 16384
#define STG_B_BYTES 32768
#define STG_BYTES   (STG_A_BYTES + STG_B_BYTES)
#define STG_FLOATS  (STG_BYTES / 4)
#define GEMM_SMEM   (4 * STG_BYTES)
#define NKT 50

__global__ void __launch_bounds__(256, 1)
gemm_tc_k(int M) {
    extern __shared__ float smemf[];
    const uint32_t sbase = smem_u32(smemf);
    const int tid  = threadIdx.x;
    const int lane = tid & 31;
    const int warp = tid >> 5;
    const int wm = warp >> 2;
    const int wn = warp & 3;
    const int nb = blockIdx.x;
    const int mb = blockIdx.y;
    const int m0 = mb * 128;
    const int n0 = nb * 256;

    const float* Abase = g_Af  + (size_t)mb * 204800;
    const float* Bbase = g_W1p + (size_t)nb * 409600;

    float acc[4][8][4];
    #pragma unroll
    for (int i = 0; i < 4; i++)
        #pragma unroll
        for (int j = 0; j < 8; j++)
            #pragma unroll
            for (int q = 0; q < 4; q++) acc[i][j][q] = 0.0f;

    auto issue = [&](int kt, int slot) {
        const uint32_t sa = sbase + slot * STG_BYTES;
        const float* ga = Abase + (size_t)kt * 4096;
        #pragma unroll
        for (int q = 0; q < 4; q++)
            CP_ASYNC16(sa + tid * 16 + q * 4096, ga + tid * 4 + q * 1024);
        const uint32_t sb = sa + STG_A_BYTES;
        const float* gb = Bbase + (size_t)kt * 8192;
        #pragma unroll
        for (int q = 0; q < 8; q++)
            CP_ASYNC16(sb + tid * 16 + q * 4096, gb + tid * 4 + q * 1024);
    };

    #pragma unroll
    for (int p = 0; p < 4; p++) { issue(p, p); CP_COMMIT(); }

    for (int kt = 0; kt < NKT; ++kt) {
        CP_WAIT(2);
        __syncthreads();
        const float* ps = smemf + (kt & 3) * STG_FLOATS;
        const float* pa = ps;
        const float* pb = ps + 4096;
        #pragma unroll
        for (int s = 0; s < 4; s++) {
            uint4 afr[4], bfr[4];
            #pragma unroll
            for (int im = 0; im < 4; im++) {
                int i = wm * 4 + im;
                afr[im] = *(const uint4*)(pa + ((s * 8 + i) * 32 + lane) * 4);
            }
            #pragma unroll
            for (int jj = 0; jj < 4; jj++) {
                int j2 = wn * 4 + jj;
                bfr[jj] = *(const uint4*)(pb + ((s * 16 + j2) * 32 + lane) * 4);
            }
            #pragma unroll
            for (int im = 0; im < 4; im++)
                #pragma unroll
                for (int jj = 0; jj < 4; jj++) {
                    mma_tf32(acc[im][jj * 2 + 0], (const unsigned*)&afr[im], bfr[jj].x, bfr[jj].y);
                    mma_tf32(acc[im][jj * 2 + 1], (const unsigned*)&afr[im], bfr[jj].z, bfr[jj].w);
                }
        }
        __syncthreads();
        if (kt + 4 < NKT) issue(kt + 4, kt & 3);
        CP_COMMIT();
    }

    const int rl = lane >> 2;
    const int cl2 = (lane & 3) * 2;
    #pragma unroll
    for (int im = 0; im < 4; im++) {
        int row = m0 + (wm * 4 + im) * 16 + rl;
        #pragma unroll
        for (int jn = 0; jn < 8; jn++) {
            int col = n0 + (wn * 8 + jn) * 8 + cl2;
            float* p = g_H + (size_t)row * NPAD + col;
            if (row < M)     *(float2*)p              = make_float2(acc[im][jn][0], acc[im][jn][1]);
            if (row + 8 < M) *(float2*)(p + 8 * NPAD) = make_float2(acc[im][jn][2], acc[im][jn][3]);
        }
    }
}

// ---------------------------------------------------------------------------
// SpMM layer 1
// ---------------------------------------------------------------------------
__global__ void spmm1_k(const int* __restrict__ rows, const int* __restrict__ cols, int E) {
    int e = blockIdx.x * blockDim.x + threadIdx.x;
    if (e >= E) return;
    int col = cols[e];
    int row = rows[e];
    unsigned r = (unsigned)col / NNODES;
    int n = col - (int)r * NNODES;
    float v = 1.0f / (float)g_cnt[col];
    const float4* src = (const float4*)(g_H + (size_t)n * NPAD + r * WS);
    float* dst = g_h1 + (size_t)row * WS;
    #pragma unroll
    for (int q = 0; q < 4; q++) {
        float4 x = src[q];
        red_add_v4(dst + q * 4, v * x.x, v * x.y, v * x.z, v * x.w);
    }
}

__global__ void biasrelu_k(const float* __restrict__ bias1) {
    int i = blockIdx.x * blockDim.x + threadIdx.x;
    if (i >= NNODES * WS) return;
    float x = g_h1[i] + bias1[i & (WS - 1)];
    g_h1[i] = (x > 0.0f) ? x : 0.0f;
}

// ---------------------------------------------------------------------------
// SpMM layer 2: 16 threads per edge, thread t covers classes 4t..4t+3,
// one red.add.v4 per thread into padded g_out2 (52-col rows, 16B aligned).
// w2 in smem padded to [r][16][52] so LDS.128 is aligned.
// ---------------------------------------------------------------------------
#define W2P_ELEMS (NRELS * WS * NCPAD)        // 39104
#define W2P_SMEM  (W2P_ELEMS * 4)             // 156416 B

__global__ void __launch_bounds__(1024)
spmm2_k(const int* __restrict__ rows, const int* __restrict__ cols, int E) {
    extern __shared__ float w2p[];
    for (int i = threadIdx.x; i < W2P_ELEMS; i += blockDim.x) {
        int r   = i / (WS * NCPAD);
        int rem = i - r * (WS * NCPAD);
        int k   = rem / NCPAD;
        int c   = rem - k * NCPAD;
        w2p[i] = (c < NCLS) ? g_w2[(r * WS + k) * NCLS + c] : 0.0f;
    }
    __syncthreads();

    const int lane = threadIdx.x & 31;
    const int sub  = lane >> 4;       // 0/1: which of two edges in this warp
    const int t    = lane & 15;       // class group
    const int gw = (blockIdx.x * blockDim.x + threadIdx.x) >> 5;
    const int nw = (gridDim.x * blockDim.x) >> 5;

    for (int eb = gw * 2; eb < E; eb += nw * 2) {
        int e = eb + sub;
        if (e >= E) continue;
        int col = cols[e];
        int row = rows[e];
        unsigned r = (unsigned)col / NNODES;
        int n = col - (int)r * NNODES;
        float v = 1.0f / (float)g_cnt[col];
        const float4* hp = (const float4*)(g_h1 + (size_t)n * WS);
        float h[16];
        *(float4*)&h[0]  = hp[0];
        *(float4*)&h[4]  = hp[1];
        *(float4*)&h[8]  = hp[2];
        *(float4*)&h[12] = hp[3];
        if (t < 13) {
            const float* w = w2p + r * (WS * NCPAD) + t * 4;
            float a0 = 0.f, a1 = 0.f, a2 = 0.f, a3 = 0.f;
            #pragma unroll
            for (int k = 0; k < 16; k++) {
                float4 wk = *(const float4*)(w + k * NCPAD);
                a0 += h[k] * wk.x;
                a1 += h[k] * wk.y;
                a2 += h[k] * wk.z;
                a3 += h[k] * wk.w;
            }
            red_add_v4(g_out2 + (size_t)row * NCPAD + t * 4, v * a0, v * a1, v * a2, v * a3);
        }
    }
}

// ---------------------------------------------------------------------------
// finalize: out = g_out2[:, :50] + bias2
// ---------------------------------------------------------------------------
__global__ void finalize_k(float* __restrict__ out, const float* __restrict__ bias2) {
    int i = blockIdx.x * blockDim.x + threadIdx.x;
    if (i >= NNODES * NCLS) return;
    int n = i / NCLS;
    int c = i - n * NCLS;
    out[i] = g_out2[(size_t)n * NCPAD + c] + bias2[c];
}

// ---------------------------------------------------------------------------
// launch
// ---------------------------------------------------------------------------
extern "C" void kernel_launch(void* const* d_in, const int* in_sizes, int n_in,
                              void* d_out, int out_size) {
    const float* emb    = (const float*)d_in[0];
    const float* comps1 = (const float*)d_in[1];
    const float* bases1 = (const float*)d_in[2];
    const float* comps2 = (const float*)d_in[3];
    const float* bases2 = (const float*)d_in[4];
    const float* bias1  = (const float*)d_in[5];
    const float* bias2  = (const float*)d_in[6];
    const int*   rows   = (const int*)d_in[7];
    const int*   cols   = (const int*)d_in[8];
    float*       out    = (float*)d_out;
    int E = in_sizes[7];

    static int attr_set = 0;
    if (!attr_set) {
        cudaFuncSetAttribute(gemm_tc_k, cudaFuncAttributeMaxDynamicSharedMemorySize, GEMM_SMEM);
        cudaFuncSetAttribute(spmm2_k, cudaFuncAttributeMaxDynamicSharedMemorySize, W2P_SMEM);
        attr_set = 1;
    }

    // order chosen so the GEMM sits at the profiler's captured launch index (3)
    cvtA_k<<<(AF_U4 + 255) / 256, 256>>>(emb);                        // 0
    pack_w1_k<<<(NPAD * EMB + 255) / 256, 256>>>(comps1, bases1);     // 1
    zero_scratch_k<<<(ZTOT + 255) / 256, 256>>>();                    // 2
    {
        dim3 grid(NPAD / 256, MBLKS);  // (3, 391)
        gemm_tc_k<<<grid, 256, GEMM_SMEM>>>(NNODES);                  // 3  <- profiled
    }
    count_k<<<(E + 255) / 256, 256>>>(cols, E);                       // 4
    pack_w2_k<<<(NRELS * WS * NCLS + 255) / 256, 256>>>(comps2, bases2); // 5
    spmm1_k<<<(E + 255) / 256, 256>>>(rows, cols, E);                 // 6
    biasrelu_k<<<(NNODES * WS + 255) / 256, 256>>>(bias1);            // 7
    spmm2_k<<<148, 1024, W2P_SMEM>>>(rows, cols, E);                  // 8
    finalize_k<<<(NNODES * NCLS + 255) / 256, 256>>>(out, bias2);     // 9
}

// round 12
// speedup vs baseline: 2.8631x; 1.0044x over previous
#include <cuda_runtime.h>
#include <cstdint>
#include <cstddef>

// Problem constants
#define NNODES 50000
#define NRELS  47
#define EMB    1600
#define WS     16
#define NCLS   50
#define NCPAD  52             // padded classes so 4-col groups are 16B aligned
#define NBASES 40
#define W1COLS (NRELS * WS)   // 752
#define NPAD   768            // padded N (752 -> 768, zero pad)
#define MBLKS  391            // ceil(50000/128)

// Scratch (device globals; no allocation allowed)
__device__ int   g_cnt[NRELS * NNODES];                   // 9.4 MB
__device__ float g_W1p[(size_t)NPAD * EMB];               // 4.9 MB  fragment-order tf32
__device__ float g_Af[(size_t)MBLKS * 200 * 1024];        // 320 MB  fragment-order tf32 A
__device__ float g_H[(size_t)NNODES * NPAD];              // 153.6 MB [M][NPAD]
__device__ float g_h1[NNODES * WS];                       // 3.2 MB
__device__ float g_w2[NRELS * WS * NCLS];                 // 150.4 KB
__device__ float g_out2[(size_t)NNODES * NCPAD];          // 10.4 MB padded output accum

// ---------------------------------------------------------------------------
// helpers
// ---------------------------------------------------------------------------
__device__ __forceinline__ void red_add_v4(float* p, float a, float b, float c, float d) {
    asm volatile("red.global.add.v4.f32 [%0], {%1,%2,%3,%4};"
                 :: "l"(p), "f"(a), "f"(b), "f"(c), "f"(d) : "memory");
}
__device__ __forceinline__ unsigned f2tf(float f) {
    unsigned r;
    asm("cvt.rna.tf32.f32 %0, %1;" : "=r"(r) : "f"(f));
    return r;
}
__device__ __forceinline__ uint32_t smem_u32(const void* p) {
    uint32_t a;
    asm("{ .reg .u64 t; cvta.to.shared.u64 t, %1; cvt.u32.u64 %0, t; }" : "=r"(a) : "l"(p));
    return a;
}
__device__ __forceinline__ void mma_tf32(float* c, const unsigned* a, unsigned b0, unsigned b1) {
    asm volatile(
        "mma.sync.aligned.m16n8k8.row.col.f32.tf32.tf32.f32 "
        "{%0,%1,%2,%3}, {%4,%5,%6,%7}, {%8,%9}, {%0,%1,%2,%3};"
        : "+f"(c[0]), "+f"(c[1]), "+f"(c[2]), "+f"(c[3])
        : "r"(a[0]), "r"(a[1]), "r"(a[2]), "r"(a[3]), "r"(b0), "r"(b1));
}
#define CP_ASYNC16(sm, gp) \
    asm volatile("cp.async.cg.shared.global [%0], [%1], 16;" :: "r"(sm), "l"(gp) : "memory")
#define CP_COMMIT() asm volatile("cp.async.commit_group;" ::: "memory")
#define CP_WAIT(n)  asm volatile("cp.async.wait_group %0;" :: "n"(n) : "memory")

// ---------------------------------------------------------------------------
// zero / init
// ---------------------------------------------------------------------------
#define ZTOT (NNODES * NCPAD)
__global__ void zero_scratch_k() {
    int i = blockIdx.x * blockDim.x + threadIdx.x;
    if (i < NRELS * NNODES) g_cnt[i] = 0;
    if (i < NNODES * WS)    g_h1[i]  = 0.0f;
    if (i < ZTOT)           g_out2[i] = 0.0f;
}

// ---------------------------------------------------------------------------
// per-column degree count
// ---------------------------------------------------------------------------
__global__ void count_k(const int* __restrict__ cols, int E) {
    int i = blockIdx.x * blockDim.x + threadIdx.x;
    if (i < E) atomicAdd(&g_cnt[cols[i]], 1);
}

// ---------------------------------------------------------------------------
// A conversion: emb (row-major fp32) -> g_Af (fragment-order tf32).
// ---------------------------------------------------------------------------
#define AF_U4 (MBLKS * 200 * 8 * 32)    // 20,019,200 uint4

__global__ void cvtA_k(const float* __restrict__ A) {
    unsigned idx = blockIdx.x * blockDim.x + threadIdx.x;
    if (idx >= AF_U4) return;
    int l  = idx & 31;
    int i  = (idx >> 5) & 7;
    int sg = (idx >> 8) % 200;
    int mb = idx / (200 * 256);
    int row = mb * 128 + i * 16 + (l >> 2);
    int k   = sg * 8 + (l & 3);
    bool ok0 = row < NNODES;
    bool ok1 = (row + 8) < NNODES;
    const float* p0 = A + (size_t)row * EMB + k;
    const float* p1 = A + (size_t)(row + 8) * EMB + k;
    uint4 v;
    v.x = ok0 ? f2tf(p0[0]) : 0u;
    v.y = ok1 ? f2tf(p1[0]) : 0u;
    v.z = ok0 ? f2tf(p0[4]) : 0u;
    v.w = ok1 ? f2tf(p1[4]) : 0u;
    ((uint4*)g_Af)[idx] = v;
}

// ---------------------------------------------------------------------------
// weight packing (fragment-order tf32 for W1)
// ---------------------------------------------------------------------------
__global__ void pack_w1_k(const float* __restrict__ comps1, const float* __restrict__ bases1) {
    int idx = blockIdx.x * blockDim.x + threadIdx.x;
    if (idx >= NPAD * EMB) return;
    int slot = idx & 3;
    int lane = (idx >> 2) & 31;
    int jp   = (idx >> 7) & 15;
    int sg   = (idx >> 11) % 200;
    int nb   = idx / 409600;
    int j = jp * 2 + (slot >> 1);
    int n = nb * 256 + j * 8 + (lane >> 2);
    int k = sg * 8 + ((slot & 1) << 2) + (lane & 3);
    if (n >= W1COLS) { g_W1p[idx] = 0.0f; return; }
    int r = n / WS;
    int o = n - r * WS;
    float s = 0.0f;
    #pragma unroll 8
    for (int b = 0; b < NBASES; b++)
        s += comps1[r * NBASES + b] * bases1[((size_t)b * EMB + k) * WS + o];
    g_W1p[idx] = __uint_as_float(f2tf(s));
}

__global__ void pack_w2_k(const float* __restrict__ comps2, const float* __restrict__ bases2) {
    int idx = blockIdx.x * blockDim.x + threadIdx.x;
    if (idx >= NRELS * WS * NCLS) return;
    int r   = idx / (WS * NCLS);
    int rem = idx - r * (WS * NCLS);
    int k   = rem / NCLS;
    int c   = rem - k * NCLS;
    float s = 0.0f;
    #pragma unroll 8
    for (int b = 0; b < NBASES; b++)
        s += comps2[r * NBASES + b] * bases2[(b * WS + k) * NCLS + c];
    g_w2[idx] = s;
}

// ---------------------------------------------------------------------------
// TF32 tensor-core GEMM (mma.sync), fragment-order operands via cp.async.
// Single-sync mainloop: issue stage kt+3 right after the top barrier (its
// target slot (kt-1)&3 was fully consumed before that barrier), then compute.
// ---------------------------------------------------------------------------
#define STG_A_BYTES 16384
#define STG_B_BYTES 32768
#define STG_BYTES   (STG_A_BYTES + STG_B_BYTES)
#define STG_FLOATS  (STG_BYTES / 4)
#define GEMM_SMEM   (4 * STG_BYTES)
#define NKT 50

__global__ void __launch_bounds__(256, 1)
gemm_tc_k(int M) {
    extern __shared__ float smemf[];
    const uint32_t sbase = smem_u32(smemf);
    const int tid  = threadIdx.x;
    const int lane = tid & 31;
    const int warp = tid >> 5;
    const int wm = warp >> 2;
    const int wn = warp & 3;
    const int nb = blockIdx.x;
    const int mb = blockIdx.y;
    const int m0 = mb * 128;
    const int n0 = nb * 256;

    const float* Abase = g_Af  + (size_t)mb * 204800;
    const float* Bbase = g_W1p + (size_t)nb * 409600;

    float acc[4][8][4];
    #pragma unroll
    for (int i = 0; i < 4; i++)
        #pragma unroll
        for (int j = 0; j < 8; j++)
            #pragma unroll
            for (int q = 0; q < 4; q++) acc[i][j][q] = 0.0f;

    auto issue = [&](int kt, int slot) {
        const uint32_t sa = sbase + slot * STG_BYTES;
        const float* ga = Abase + (size_t)kt * 4096;
        #pragma unroll
        for (int q = 0; q < 4; q++)
            CP_ASYNC16(sa + tid * 16 + q * 4096, ga + tid * 4 + q * 1024);
        const uint32_t sb = sa + STG_A_BYTES;
        const float* gb = Bbase + (size_t)kt * 8192;
        #pragma unroll
        for (int q = 0; q < 8; q++)
            CP_ASYNC16(sb + tid * 16 + q * 4096, gb + tid * 4 + q * 1024);
    };

    // prologue: 3 stages in flight
    #pragma unroll
    for (int p = 0; p < 3; p++) { issue(p, p); CP_COMMIT(); }

    for (int kt = 0; kt < NKT; ++kt) {
        CP_WAIT(2);
        __syncthreads();
        if (kt + 3 < NKT) issue(kt + 3, (kt + 3) & 3);
        CP_COMMIT();

        const float* ps = smemf + (kt & 3) * STG_FLOATS;
        const float* pa = ps;
        const float* pb = ps + 4096;
        #pragma unroll
        for (int s = 0; s < 4; s++) {
            uint4 afr[4], bfr[4];
            #pragma unroll
            for (int im = 0; im < 4; im++) {
                int i = wm * 4 + im;
                afr[im] = *(const uint4*)(pa + ((s * 8 + i) * 32 + lane) * 4);
            }
            #pragma unroll
            for (int jj = 0; jj < 4; jj++) {
                int j2 = wn * 4 + jj;
                bfr[jj] = *(const uint4*)(pb + ((s * 16 + j2) * 32 + lane) * 4);
            }
            #pragma unroll
            for (int im = 0; im < 4; im++)
                #pragma unroll
                for (int jj = 0; jj < 4; jj++) {
                    mma_tf32(acc[im][jj * 2 + 0], (const unsigned*)&afr[im], bfr[jj].x, bfr[jj].y);
                    mma_tf32(acc[im][jj * 2 + 1], (const unsigned*)&afr[im], bfr[jj].z, bfr[jj].w);
                }
        }
    }

    const int rl = lane >> 2;
    const int cl2 = (lane & 3) * 2;
    #pragma unroll
    for (int im = 0; im < 4; im++) {
        int row = m0 + (wm * 4 + im) * 16 + rl;
        #pragma unroll
        for (int jn = 0; jn < 8; jn++) {
            int col = n0 + (wn * 8 + jn) * 8 + cl2;
            float* p = g_H + (size_t)row * NPAD + col;
            if (row < M)     *(float2*)p              = make_float2(acc[im][jn][0], acc[im][jn][1]);
            if (row + 8 < M) *(float2*)(p + 8 * NPAD) = make_float2(acc[im][jn][2], acc[im][jn][3]);
        }
    }
}

// ---------------------------------------------------------------------------
// SpMM layer 1
// ---------------------------------------------------------------------------
__global__ void spmm1_k(const int* __restrict__ rows, const int* __restrict__ cols, int E) {
    int e = blockIdx.x * blockDim.x + threadIdx.x;
    if (e >= E) return;
    int col = cols[e];
    int row = rows[e];
    unsigned r = (unsigned)col / NNODES;
    int n = col - (int)r * NNODES;
    float v = 1.0f / (float)g_cnt[col];
    const float4* src = (const float4*)(g_H + (size_t)n * NPAD + r * WS);
    float* dst = g_h1 + (size_t)row * WS;
    #pragma unroll
    for (int q = 0; q < 4; q++) {
        float4 x = src[q];
        red_add_v4(dst + q * 4, v * x.x, v * x.y, v * x.z, v * x.w);
    }
}

__global__ void biasrelu_k(const float* __restrict__ bias1) {
    int i = blockIdx.x * blockDim.x + threadIdx.x;
    if (i >= NNODES * WS) return;
    float x = g_h1[i] + bias1[i & (WS - 1)];
    g_h1[i] = (x > 0.0f) ? x : 0.0f;
}

// ---------------------------------------------------------------------------
// SpMM layer 2: 16 threads per edge, thread t covers classes 4t..4t+3,
// one red.add.v4 per thread into padded g_out2 (52-col rows, 16B aligned).
// ---------------------------------------------------------------------------
#define W2P_ELEMS (NRELS * WS * NCPAD)        // 39104
#define W2P_SMEM  (W2P_ELEMS * 4)             // 156416 B

__global__ void __launch_bounds__(1024)
spmm2_k(const int* __restrict__ rows, const int* __restrict__ cols, int E) {
    extern __shared__ float w2p[];
    for (int i = threadIdx.x; i < W2P_ELEMS; i += blockDim.x) {
        int r   = i / (WS * NCPAD);
        int rem = i - r * (WS * NCPAD);
        int k   = rem / NCPAD;
        int c   = rem - k * NCPAD;
        w2p[i] = (c < NCLS) ? g_w2[(r * WS + k) * NCLS + c] : 0.0f;
    }
    __syncthreads();

    const int lane = threadIdx.x & 31;
    const int sub  = lane >> 4;
    const int t    = lane & 15;
    const int gw = (blockIdx.x * blockDim.x + threadIdx.x) >> 5;
    const int nw = (gridDim.x * blockDim.x) >> 5;

    for (int eb = gw * 2; eb < E; eb += nw * 2) {
        int e = eb + sub;
        if (e >= E) continue;
        int col = cols[e];
        int row = rows[e];
        unsigned r = (unsigned)col / NNODES;
        int n = col - (int)r * NNODES;
        float v = 1.0f / (float)g_cnt[col];
        const float4* hp = (const float4*)(g_h1 + (size_t)n * WS);
        float h[16];
        *(float4*)&h[0]  = hp[0];
        *(float4*)&h[4]  = hp[1];
        *(float4*)&h[8]  = hp[2];
        *(float4*)&h[12] = hp[3];
        if (t < 13) {
            const float* w = w2p + r * (WS * NCPAD) + t * 4;
            float a0 = 0.f, a1 = 0.f, a2 = 0.f, a3 = 0.f;
            #pragma unroll
            for (int k = 0; k < 16; k++) {
                float4 wk = *(const float4*)(w + k * NCPAD);
                a0 += h[k] * wk.x;
                a1 += h[k] * wk.y;
                a2 += h[k] * wk.z;
                a3 += h[k] * wk.w;
            }
            red_add_v4(g_out2 + (size_t)row * NCPAD + t * 4, v * a0, v * a1, v * a2, v * a3);
        }
    }
}

// ---------------------------------------------------------------------------
// finalize: out = g_out2[:, :50] + bias2
// ---------------------------------------------------------------------------
__global__ void finalize_k(float* __restrict__ out, const float* __restrict__ bias2) {
    int i = blockIdx.x * blockDim.x + threadIdx.x;
    if (i >= NNODES * NCLS) return;
    int n = i / NCLS;
    int c = i - n * NCLS;
    out[i] = g_out2[(size_t)n * NCPAD + c] + bias2[c];
}

// ---------------------------------------------------------------------------
// launch
// ---------------------------------------------------------------------------
extern "C" void kernel_launch(void* const* d_in, const int* in_sizes, int n_in,
                              void* d_out, int out_size) {
    const float* emb    = (const float*)d_in[0];
    const float* comps1 = (const float*)d_in[1];
    const float* bases1 = (const float*)d_in[2];
    const float* comps2 = (const float*)d_in[3];
    const float* bases2 = (const float*)d_in[4];
    const float* bias1  = (const float*)d_in[5];
    const float* bias2  = (const float*)d_in[6];
    const int*   rows   = (const int*)d_in[7];
    const int*   cols   = (const int*)d_in[8];
    float*       out    = (float*)d_out;
    int E = in_sizes[7];

    static int attr_set = 0;
    if (!attr_set) {
        cudaFuncSetAttribute(gemm_tc_k, cudaFuncAttributeMaxDynamicSharedMemorySize, GEMM_SMEM);
        cudaFuncSetAttribute(spmm2_k, cudaFuncAttributeMaxDynamicSharedMemorySize, W2P_SMEM);
        attr_set = 1;
    }

    // order chosen so the GEMM sits at the profiler's captured launch index (3)
    cvtA_k<<<(AF_U4 + 255) / 256, 256>>>(emb);                        // 0
    pack_w1_k<<<(NPAD * EMB + 255) / 256, 256>>>(comps1, bases1);     // 1
    zero_scratch_k<<<(ZTOT + 255) / 256, 256>>>();                    // 2
    {
        dim3 grid(NPAD / 256, MBLKS);  // (3, 391)
        gemm_tc_k<<<grid, 256, GEMM_SMEM>>>(NNODES);                  // 3  <- profiled
    }
    count_k<<<(E + 255) / 256, 256>>>(cols, E);                       // 4
    pack_w2_k<<<(NRELS * WS * NCLS + 255) / 256, 256>>>(comps2, bases2); // 5
    spmm1_k<<<(E + 255) / 256, 256>>>(rows, cols, E);                 // 6
    biasrelu_k<<<(NNODES * WS + 255) / 256, 256>>>(bias1);            // 7
    spmm2_k<<<148, 1024, W2P_SMEM>>>(rows, cols, E);                  // 8
    finalize_k<<<(NNODES * NCLS + 255) / 256, 256>>>(out, bias2);     // 9
}